// round 1
// baseline (speedup 1.0000x reference)
#include <cuda_runtime.h>
#include <math.h>
#include <stdint.h>

#define BATCH  4
#define SEQ    2048
#define EMB    2048
#define NHEAD  16
#define HDIM   128
#define MTOT   (BATCH*SEQ)      // 8192
#define KDIM   2048

// ---------------- scratch (device globals: allocation-free rule) ----------------
__device__ float g_Q[BATCH*NHEAD*SEQ*HDIM];   // [B,H,S,D] after rope
__device__ float g_K[BATCH*NHEAD*SEQ*HDIM];
__device__ float g_V[BATCH*NHEAD*SEQ*HDIM];
__device__ float g_C[BATCH*SEQ*EMB];          // attention context [B,S,E]

// =================================================================================
// GEMM: C[m,n] = sum_k A[m,k] * W[n,k]    (A: [M,2048], W: [2048,2048], row-major)
// 128x128 block tile, 256 threads, 8x8 per thread, KT=16.
// MODE 0: plain store to D0[m*2048+n]
// MODE 1: QKV — blockIdx.z selects W/dst, epilogue applies RoPE (z<2) and writes
//         transposed [B,H,S,D] layout.
// =================================================================================
template<int MODE>
__global__ void __launch_bounds__(256) gemm_k(
    const float* __restrict__ A,
    const float* __restrict__ W0, const float* __restrict__ W1, const float* __restrict__ W2,
    float* __restrict__ D0, float* __restrict__ D1, float* __restrict__ D2)
{
    const float* B = W0;
    float* D = D0;
    int z = 0;
    if (MODE == 1) {
        z = blockIdx.z;
        if (z == 1) { B = W1; D = D1; }
        else if (z == 2) { B = W2; D = D2; }
    }

    __shared__ float As[16][132];
    __shared__ float Bs[16][132];

    const int tid = threadIdx.x;
    const int ty = tid >> 4;          // 0..15
    const int tx = tid & 15;          // 0..15
    const int m0 = blockIdx.y * 128;
    const int n0 = blockIdx.x * 128;

    float acc[8][8];
    #pragma unroll
    for (int i = 0; i < 8; i++)
        #pragma unroll
        for (int j = 0; j < 8; j++) acc[i][j] = 0.f;

    const int lrow = tid >> 2;              // 0..63
    const int lkc  = (tid & 3) * 4;         // 0,4,8,12

    for (int kt = 0; kt < KDIM; kt += 16) {
        #pragma unroll
        for (int it = 0; it < 2; it++) {
            int row = lrow + it * 64;
            float4 va = *(const float4*)(A + (size_t)(m0 + row) * KDIM + kt + lkc);
            As[lkc + 0][row] = va.x; As[lkc + 1][row] = va.y;
            As[lkc + 2][row] = va.z; As[lkc + 3][row] = va.w;
            float4 vb = *(const float4*)(B + (size_t)(n0 + row) * KDIM + kt + lkc);
            Bs[lkc + 0][row] = vb.x; Bs[lkc + 1][row] = vb.y;
            Bs[lkc + 2][row] = vb.z; Bs[lkc + 3][row] = vb.w;
        }
        __syncthreads();

        #pragma unroll
        for (int kk = 0; kk < 16; kk++) {
            float a[8], b[8];
            *(float4*)&a[0] = *(const float4*)&As[kk][ty * 8];
            *(float4*)&a[4] = *(const float4*)&As[kk][ty * 8 + 4];
            *(float4*)&b[0] = *(const float4*)&Bs[kk][tx * 8];
            *(float4*)&b[4] = *(const float4*)&Bs[kk][tx * 8 + 4];
            #pragma unroll
            for (int i = 0; i < 8; i++)
                #pragma unroll
                for (int j = 0; j < 8; j++)
                    acc[i][j] += a[i] * b[j];
        }
        __syncthreads();
    }

    if (MODE == 0) {
        #pragma unroll
        for (int i = 0; i < 8; i++) {
            int m = m0 + ty * 8 + i;
            float* dst = D + (size_t)m * 2048 + n0 + tx * 8;
            float4 r0 = make_float4(acc[i][0], acc[i][1], acc[i][2], acc[i][3]);
            float4 r1 = make_float4(acc[i][4], acc[i][5], acc[i][6], acc[i][7]);
            *(float4*)dst = r0;
            *(float4*)(dst + 4) = r1;
        }
    } else {
        const int nb = n0 + tx * 8;
        const int h  = nb >> 7;
        const int dd = nb & 127;            // 8 cols stay within one head
        // rope inv-freq for the 4 pairs this thread owns
        float invf[4];
        #pragma unroll
        for (int p = 0; p < 4; p++) {
            int pi = (dd >> 1) + p;
            invf[p] = powf(10000.0f, -(float)pi * (1.0f / 64.0f));
        }
        #pragma unroll
        for (int i = 0; i < 8; i++) {
            int m = m0 + ty * 8 + i;
            int bb = m >> 11;
            int s  = m & 2047;
            float v[8];
            if (z < 2) {
                #pragma unroll
                for (int p = 0; p < 4; p++) {
                    float ang = (float)s * invf[p];
                    float sn, cs;
                    sincosf(ang, &sn, &cs);
                    float x1 = acc[i][2 * p], x2 = acc[i][2 * p + 1];
                    v[2 * p]     = x1 * cs - x2 * sn;
                    v[2 * p + 1] = x2 * cs + x1 * sn;
                }
            } else {
                #pragma unroll
                for (int j = 0; j < 8; j++) v[j] = acc[i][j];
            }
            float* dst = D + ((size_t)(bb * NHEAD + h) * SEQ + s) * HDIM + dd;
            *(float4*)dst       = make_float4(v[0], v[1], v[2], v[3]);
            *(float4*)(dst + 4) = make_float4(v[4], v[5], v[6], v[7]);
        }
    }
}

// =================================================================================
// Flash attention (fp32, causal). BM=BN=64, D=128, 256 threads.
// Smem: Qs,Ks transposed [128][68]; Vs [64][128]; Ps (P^T) [64][68].
// Thread (ty,tx) 16x16 grid: scores 4x4 frag, O 4 rows x 8 cols.
// =================================================================================
#define FSM_Q   0
#define FSM_K   (128*68)
#define FSM_V   (2*128*68)
#define FSM_P   (2*128*68 + 64*128)
#define FSM_FLT (2*128*68 + 64*128 + 64*68)
#define FSM_BYTES (FSM_FLT * 4)

__global__ void __launch_bounds__(256) flash_kernel(
    const float* __restrict__ Qg, const float* __restrict__ Kg,
    const float* __restrict__ Vg, float* __restrict__ Cg)
{
    extern __shared__ float sm[];
    float* Qs = sm + FSM_Q;
    float* Ks = sm + FSM_K;
    float* Vs = sm + FSM_V;
    float* Ps = sm + FSM_P;

    const int tid = threadIdx.x;
    const int ty = tid >> 4, tx = tid & 15;
    const int q0 = blockIdx.x * 64;
    const int b  = blockIdx.y >> 4, h = blockIdx.y & 15;
    const size_t bh = ((size_t)(b * NHEAD + h)) * SEQ * HDIM;
    const float* Qp = Qg + bh;
    const float* Kp = Kg + bh;
    const float* Vp = Vg + bh;

    const int ml = tid >> 3;       // 0..31
    const int kg = tid & 7;        // 0..7

    // load Q tile transposed: Qs[k*68 + m]
    #pragma unroll
    for (int mp = 0; mp < 64; mp += 32)
        #pragma unroll
        for (int kp = 0; kp < 32; kp += 8) {
            int m  = ml + mp;
            int k4 = (kg + kp) * 4;
            float4 v = *(const float4*)(Qp + (size_t)(q0 + m) * HDIM + k4);
            Qs[(k4 + 0) * 68 + m] = v.x;
            Qs[(k4 + 1) * 68 + m] = v.y;
            Qs[(k4 + 2) * 68 + m] = v.z;
            Qs[(k4 + 3) * 68 + m] = v.w;
        }

    float o[4][8];
    #pragma unroll
    for (int i = 0; i < 4; i++)
        #pragma unroll
        for (int j = 0; j < 8; j++) o[i][j] = 0.f;
    float mrow[4] = {-1e30f, -1e30f, -1e30f, -1e30f};
    float lrow[4] = {0.f, 0.f, 0.f, 0.f};
    const float scale = 0.08838834764831845f;   // 1/sqrt(128)

    const int nIter = (q0 >> 6) + 1;
    for (int it = 0; it < nIter; it++) {
        const int j0 = it * 64;
        __syncthreads();   // previous iteration done with Ks/Vs/Ps

        // K transposed
        #pragma unroll
        for (int mp = 0; mp < 64; mp += 32)
            #pragma unroll
            for (int kp = 0; kp < 32; kp += 8) {
                int m  = ml + mp;
                int k4 = (kg + kp) * 4;
                float4 v = *(const float4*)(Kp + (size_t)(j0 + m) * HDIM + k4);
                Ks[(k4 + 0) * 68 + m] = v.x;
                Ks[(k4 + 1) * 68 + m] = v.y;
                Ks[(k4 + 2) * 68 + m] = v.z;
                Ks[(k4 + 3) * 68 + m] = v.w;
            }
        // V natural
        #pragma unroll
        for (int i2 = 0; i2 < 8; i2++) {
            int f = tid + 256 * i2;
            int m = f >> 5;
            int d4 = (f & 31) * 4;
            *(float4*)(Vs + m * 128 + d4) =
                *(const float4*)(Vp + (size_t)(j0 + m) * HDIM + d4);
        }
        __syncthreads();

        // scores: s[i][j] = sum_k Q[q0+ty*4+i][k] * K[j0+tx*4+j][k]
        float s[4][4];
        #pragma unroll
        for (int i = 0; i < 4; i++)
            #pragma unroll
            for (int j = 0; j < 4; j++) s[i][j] = 0.f;

        #pragma unroll 8
        for (int kk = 0; kk < 128; kk++) {
            float4 a  = *(const float4*)(Qs + kk * 68 + ty * 4);
            float4 bv = *(const float4*)(Ks + kk * 68 + tx * 4);
            s[0][0] += a.x * bv.x; s[0][1] += a.x * bv.y; s[0][2] += a.x * bv.z; s[0][3] += a.x * bv.w;
            s[1][0] += a.y * bv.x; s[1][1] += a.y * bv.y; s[1][2] += a.y * bv.z; s[1][3] += a.y * bv.w;
            s[2][0] += a.z * bv.x; s[2][1] += a.z * bv.y; s[2][2] += a.z * bv.z; s[2][3] += a.z * bv.w;
            s[3][0] += a.w * bv.x; s[3][1] += a.w * bv.y; s[3][2] += a.w * bv.z; s[3][3] += a.w * bv.w;
        }

        // scale + causal mask (only bites on the diagonal tile)
        #pragma unroll
        for (int i = 0; i < 4; i++)
            #pragma unroll
            for (int j = 0; j < 4; j++) {
                float v = s[i][j] * scale;
                if (j0 + tx * 4 + j > q0 + ty * 4 + i) v = -1e30f;
                s[i][j] = v;
            }

        // online softmax per row
        #pragma unroll
        for (int i = 0; i < 4; i++) {
            float mx = fmaxf(fmaxf(s[i][0], s[i][1]), fmaxf(s[i][2], s[i][3]));
            #pragma unroll
            for (int off = 1; off < 16; off <<= 1)
                mx = fmaxf(mx, __shfl_xor_sync(0xffffffffu, mx, off));
            float mnew = fmaxf(mrow[i], mx);
            float corr = expf(mrow[i] - mnew);
            float rsum = 0.f;
            #pragma unroll
            for (int j = 0; j < 4; j++) {
                float p = expf(s[i][j] - mnew);
                s[i][j] = p;
                rsum += p;
            }
            #pragma unroll
            for (int off = 1; off < 16; off <<= 1)
                rsum += __shfl_xor_sync(0xffffffffu, rsum, off);
            lrow[i] = lrow[i] * corr + rsum;
            mrow[i] = mnew;
            #pragma unroll
            for (int j = 0; j < 8; j++) o[i][j] *= corr;
        }

        // write P transposed: Ps[kk*68 + m]
        #pragma unroll
        for (int i = 0; i < 4; i++)
            #pragma unroll
            for (int j = 0; j < 4; j++)
                Ps[(tx * 4 + j) * 68 + ty * 4 + i] = s[i][j];
        __syncthreads();

        // O += P @ V
        #pragma unroll 8
        for (int kk = 0; kk < 64; kk++) {
            float4 p  = *(const float4*)(Ps + kk * 68 + ty * 4);
            float4 v0 = *(const float4*)(Vs + kk * 128 + tx * 8);
            float4 v1 = *(const float4*)(Vs + kk * 128 + tx * 8 + 4);
            o[0][0] += p.x * v0.x; o[0][1] += p.x * v0.y; o[0][2] += p.x * v0.z; o[0][3] += p.x * v0.w;
            o[0][4] += p.x * v1.x; o[0][5] += p.x * v1.y; o[0][6] += p.x * v1.z; o[0][7] += p.x * v1.w;
            o[1][0] += p.y * v0.x; o[1][1] += p.y * v0.y; o[1][2] += p.y * v0.z; o[1][3] += p.y * v0.w;
            o[1][4] += p.y * v1.x; o[1][5] += p.y * v1.y; o[1][6] += p.y * v1.z; o[1][7] += p.y * v1.w;
            o[2][0] += p.z * v0.x; o[2][1] += p.z * v0.y; o[2][2] += p.z * v0.z; o[2][3] += p.z * v0.w;
            o[2][4] += p.z * v1.x; o[2][5] += p.z * v1.y; o[2][6] += p.z * v1.z; o[2][7] += p.z * v1.w;
            o[3][0] += p.w * v0.x; o[3][1] += p.w * v0.y; o[3][2] += p.w * v0.z; o[3][3] += p.w * v0.w;
            o[3][4] += p.w * v1.x; o[3][5] += p.w * v1.y; o[3][6] += p.w * v1.z; o[3][7] += p.w * v1.w;
        }
    }

    // epilogue: ctx[b, s, h*128 + d]
    #pragma unroll
    for (int i = 0; i < 4; i++) {
        float inv = 1.0f / lrow[i];
        int srow = q0 + ty * 4 + i;
        float* dst = Cg + ((size_t)(b * SEQ + srow)) * EMB + h * HDIM + tx * 8;
        float4 r0 = make_float4(o[i][0] * inv, o[i][1] * inv, o[i][2] * inv, o[i][3] * inv);
        float4 r1 = make_float4(o[i][4] * inv, o[i][5] * inv, o[i][6] * inv, o[i][7] * inv);
        *(float4*)dst = r0;
        *(float4*)(dst + 4) = r1;
    }
}

// =================================================================================
extern "C" void kernel_launch(void* const* d_in, const int* in_sizes, int n_in,
                              void* d_out, int out_size)
{
    const float* x  = (const float*)d_in[0];
    const float* Wq = (const float*)d_in[1];
    const float* Wk = (const float*)d_in[2];
    const float* Wv = (const float*)d_in[3];
    const float* Wo = (const float*)d_in[4];
    float* out = (float*)d_out;

    float *Q, *K, *V, *C;
    cudaGetSymbolAddress((void**)&Q, g_Q);
    cudaGetSymbolAddress((void**)&K, g_K);
    cudaGetSymbolAddress((void**)&V, g_V);
    cudaGetSymbolAddress((void**)&C, g_C);

    cudaFuncSetAttribute(flash_kernel,
                         cudaFuncAttributeMaxDynamicSharedMemorySize, FSM_BYTES);

    // 1) fused QKV projection + RoPE + [B,H,S,D] transpose
    {
        dim3 grid(EMB / 128, MTOT / 128, 3);
        gemm_k<1><<<grid, 256>>>(x, Wq, Wk, Wv, Q, K, V);
    }
    // 2) causal flash attention
    {
        dim3 grid(SEQ / 64, BATCH * NHEAD);
        flash_kernel<<<grid, 256, FSM_BYTES>>>(Q, K, V, C);
    }
    // 3) output projection
    {
        dim3 grid(EMB / 128, MTOT / 128, 1);
        gemm_k<0><<<grid, 256>>>(C, Wo, Wo, Wo, out, out, out);
    }
}

// round 3
// speedup vs baseline: 2.6789x; 2.6789x over previous
#include <cuda_runtime.h>
#include <cuda_fp16.h>
#include <math.h>
#include <stdint.h>

#define BATCH  4
#define SEQ    2048
#define EMB    2048
#define NHEAD  16
#define HDIM   128
#define MTOT   (BATCH*SEQ)      // 8192
#define KDIM   2048

// ---------------- scratch (device globals: allocation-free rule) ----------------
__device__ float g_Q[BATCH*NHEAD*SEQ*HDIM];   // [B,H,S,D] after rope
__device__ float g_K[BATCH*NHEAD*SEQ*HDIM];
__device__ float g_V[BATCH*NHEAD*SEQ*HDIM];
__device__ float g_C[BATCH*SEQ*EMB];          // attention context [B,S,E]

__device__ __forceinline__ uint32_t smem_u32(const void* p) {
    uint32_t a;
    asm("{ .reg .u64 t; cvta.to.shared.u64 t, %1; cvt.u32.u64 %0, t; }" : "=r"(a) : "l"(p));
    return a;
}

#define CP_ASYNC16(dst, src) \
    asm volatile("cp.async.cg.shared.global [%0], [%1], 16;" :: "r"(dst), "l"(src))
#define CP_COMMIT() asm volatile("cp.async.commit_group;" ::: "memory")
#define CP_WAIT0()  asm volatile("cp.async.wait_group 0;" ::: "memory")

#define LDMX4(r0,r1,r2,r3, addr) \
    asm volatile("ldmatrix.sync.aligned.m8n8.x4.shared.b16 {%0,%1,%2,%3}, [%4];" \
        : "=r"(r0),"=r"(r1),"=r"(r2),"=r"(r3) : "r"(addr))

#define MMA16816(c, a0,a1,a2,a3, b0,b1) \
    asm volatile("mma.sync.aligned.m16n8k16.row.col.f32.f16.f16.f32 " \
        "{%0,%1,%2,%3}, {%4,%5,%6,%7}, {%8,%9}, {%0,%1,%2,%3};" \
        : "+f"((c)[0]),"+f"((c)[1]),"+f"((c)[2]),"+f"((c)[3]) \
        : "r"(a0),"r"(a1),"r"(a2),"r"(a3), "r"(b0),"r"(b1))

// =================================================================================
// fp16x3 mma GEMM: C[m,n] = sum_k A[m,k]*W[n,k]   (A:[M,2048], W:[2048,2048])
// BM=128, BN=64, BK=64. 8 warps as 2(M)x4(N) -> warp tile 64x16.
// cp.async fp32 staging -> convert to fp16 hi/lo SW128 buffers -> ldmatrix -> mma.
// MODE 0: plain store.  MODE 1: QKV (z=blockIdx.z), RoPE for z<2, [B,H,S,D] layout.
// =================================================================================
#define BM 128
#define BN 64
#define BK 64
#define NSTG (KDIM/BK)     // 32

// smem byte offsets
#define SA32 0              // A fp32 staging [128][64]f  = 32768
#define SB32 32768          // B fp32 staging [64][64]f   = 16384
#define SAH  49152          // A hi fp16 [128][64]h (SW128, 128B rows) = 16384
#define SAL  65536
#define SBH  81920          // B hi fp16 [64][64]h = 8192
#define SBL  90112
#define GSM  98304

template<int MODE>
__global__ void __launch_bounds__(256, 2) gemm_mma(
    const float* __restrict__ A,
    const float* __restrict__ W0, const float* __restrict__ W1, const float* __restrict__ W2,
    float* __restrict__ D0, float* __restrict__ D1, float* __restrict__ D2)
{
    extern __shared__ char sm[];
    const uint32_t sb = smem_u32(sm);

    const float* Bg = W0;
    float* D = D0;
    int z = 0;
    if (MODE == 1) {
        z = blockIdx.z;
        if (z == 1) { Bg = W1; D = D1; }
        else if (z == 2) { Bg = W2; D = D2; }
    }

    const int tid = threadIdx.x;
    const int wid = tid >> 5;
    const int lid = tid & 31;
    const int wm = wid >> 2;        // 0..1
    const int wn = wid & 3;         // 0..3
    const int m0 = blockIdx.y * BM;
    const int n0 = blockIdx.x * BN;

    float acc[4][2][4];
    #pragma unroll
    for (int i = 0; i < 4; i++)
        #pragma unroll
        for (int j = 0; j < 2; j++)
            #pragma unroll
            for (int k = 0; k < 4; k++) acc[i][j][k] = 0.f;

    // ---------------- helpers as lambdas ----------------
    auto issue_stage = [&](int s) {
        const int kt = s * BK;
        #pragma unroll
        for (int i = 0; i < 8; i++) {
            int idx = i * 256 + tid;
            int r = idx >> 4, c4 = idx & 15;
            CP_ASYNC16(sb + SA32 + r * 256 + c4 * 16,
                       (const char*)(A + (size_t)(m0 + r) * KDIM + kt + c4 * 4));
        }
        #pragma unroll
        for (int i = 0; i < 4; i++) {
            int idx = i * 256 + tid;
            int r = idx >> 4, c4 = idx & 15;
            CP_ASYNC16(sb + SB32 + r * 256 + c4 * 16,
                       (const char*)(Bg + (size_t)(n0 + r) * KDIM + kt + c4 * 4));
        }
        CP_COMMIT();
    };

    auto convert_stage = [&]() {
        #pragma unroll
        for (int i = 0; i < 12; i++) {
            int idx, src_off, hi_off;
            if (i < 8) {
                idx = i * 256 + tid;
                int r = idx >> 4, c4 = idx & 15;
                src_off = SA32 + r * 256 + c4 * 16;
                uint32_t off = (uint32_t)(r * 128 + c4 * 8);
                off ^= (off >> 3) & 0x70;
                hi_off = SAH + off;
            } else {
                idx = (i - 8) * 256 + tid;
                int r = idx >> 4, c4 = idx & 15;
                src_off = SB32 + r * 256 + c4 * 16;
                uint32_t off = (uint32_t)(r * 128 + c4 * 8);
                off ^= (off >> 3) & 0x70;
                hi_off = SBH + off;
            }
            float4 v = *(const float4*)(sm + src_off);
            __half hx = __float2half_rn(v.x);
            __half hy = __float2half_rn(v.y);
            __half hz = __float2half_rn(v.z);
            __half hw = __float2half_rn(v.w);
            __half lx = __float2half_rn(v.x - __half2float(hx));
            __half ly = __float2half_rn(v.y - __half2float(hy));
            __half lz = __float2half_rn(v.z - __half2float(hz));
            __half lw = __float2half_rn(v.w - __half2float(hw));
            __half2 h01 = __halves2half2(hx, hy), h23 = __halves2half2(hz, hw);
            __half2 l01 = __halves2half2(lx, ly), l23 = __halves2half2(lz, lw);
            uint2 hp, lp;
            hp.x = *(uint32_t*)&h01; hp.y = *(uint32_t*)&h23;
            lp.x = *(uint32_t*)&l01; lp.y = *(uint32_t*)&l23;
            *(uint2*)(sm + hi_off)         = hp;
            *(uint2*)(sm + hi_off + 16384) = lp;   // SAL-SAH == SBL-SBH == 16384? no!
        }
    };
    // NOTE: SAL-SAH = 16384, SBL-SBH = 8192 -> handle B lo offset explicitly below.

    // (convert_stage above writes lo at +16384; correct for A. For B we need +8192.
    //  To keep one code path, SBL is placed at SBH+8192; we fix by splitting loops.)

    auto convert_stage2 = [&]() {
        #pragma unroll
        for (int i = 0; i < 8; i++) {
            int idx = i * 256 + tid;
            int r = idx >> 4, c4 = idx & 15;
            float4 v = *(const float4*)(sm + SA32 + r * 256 + c4 * 16);
            uint32_t off = (uint32_t)(r * 128 + c4 * 8);
            off ^= (off >> 3) & 0x70;
            __half hx = __float2half_rn(v.x), hy = __float2half_rn(v.y);
            __half hz = __float2half_rn(v.z), hw = __float2half_rn(v.w);
            __half lx = __float2half_rn(v.x - __half2float(hx));
            __half ly = __float2half_rn(v.y - __half2float(hy));
            __half lz = __float2half_rn(v.z - __half2float(hz));
            __half lw = __float2half_rn(v.w - __half2float(hw));
            __half2 h01 = __halves2half2(hx, hy), h23 = __halves2half2(hz, hw);
            __half2 l01 = __halves2half2(lx, ly), l23 = __halves2half2(lz, lw);
            uint2 hp, lp;
            hp.x = *(uint32_t*)&h01; hp.y = *(uint32_t*)&h23;
            lp.x = *(uint32_t*)&l01; lp.y = *(uint32_t*)&l23;
            *(uint2*)(sm + SAH + off) = hp;
            *(uint2*)(sm + SAL + off) = lp;
        }
        #pragma unroll
        for (int i = 0; i < 4; i++) {
            int idx = i * 256 + tid;
            int r = idx >> 4, c4 = idx & 15;
            float4 v = *(const float4*)(sm + SB32 + r * 256 + c4 * 16);
            uint32_t off = (uint32_t)(r * 128 + c4 * 8);
            off ^= (off >> 3) & 0x70;
            __half hx = __float2half_rn(v.x), hy = __float2half_rn(v.y);
            __half hz = __float2half_rn(v.z), hw = __float2half_rn(v.w);
            __half lx = __float2half_rn(v.x - __half2float(hx));
            __half ly = __float2half_rn(v.y - __half2float(hy));
            __half lz = __float2half_rn(v.z - __half2float(hz));
            __half lw = __float2half_rn(v.w - __half2float(hw));
            __half2 h01 = __halves2half2(hx, hy), h23 = __halves2half2(hz, hw);
            __half2 l01 = __halves2half2(lx, ly), l23 = __halves2half2(lz, lw);
            uint2 hp, lp;
            hp.x = *(uint32_t*)&h01; hp.y = *(uint32_t*)&h23;
            lp.x = *(uint32_t*)&l01; lp.y = *(uint32_t*)&l23;
            *(uint2*)(sm + SBH + off) = hp;
            *(uint2*)(sm + SBL + off) = lp;
        }
    };
    (void)convert_stage; // unused (kept for clarity); convert_stage2 is the real one

    auto compute_stage = [&]() {
        const int lr = lid & 15;
        const int lc = lid >> 4;
        #pragma unroll
        for (int ks = 0; ks < 4; ks++) {
            // B fragments: one x4 covers both n8-tiles (16 n rows) for this kstep
            uint32_t boff = (uint32_t)((wn * 16 + lr) * 128 + ks * 32 + lc * 16);
            boff ^= (boff >> 3) & 0x70;
            uint32_t bh0, bh1, bh2, bh3, bl0, bl1, bl2, bl3;
            LDMX4(bh0, bh1, bh2, bh3, sb + SBH + boff);
            LDMX4(bl0, bl1, bl2, bl3, sb + SBL + boff);
            #pragma unroll
            for (int mt = 0; mt < 4; mt++) {
                uint32_t aoff = (uint32_t)((wm * 64 + mt * 16 + lr) * 128 + ks * 32 + lc * 16);
                aoff ^= (aoff >> 3) & 0x70;
                uint32_t a0, a1, a2, a3, q0, q1, q2, q3;
                LDMX4(a0, a1, a2, a3, sb + SAH + aoff);
                LDMX4(q0, q1, q2, q3, sb + SAL + aoff);
                // ntile 0: b regs {r0, r2}; ntile 1: {r1, r3}
                MMA16816(acc[mt][0], a0, a1, a2, a3, bh0, bh2);
                MMA16816(acc[mt][0], a0, a1, a2, a3, bl0, bl2);
                MMA16816(acc[mt][0], q0, q1, q2, q3, bh0, bh2);
                MMA16816(acc[mt][1], a0, a1, a2, a3, bh1, bh3);
                MMA16816(acc[mt][1], a0, a1, a2, a3, bl1, bl3);
                MMA16816(acc[mt][1], q0, q1, q2, q3, bh1, bh3);
            }
        }
    };

    // ---------------- pipeline ----------------
    issue_stage(0);
    CP_WAIT0();
    __syncthreads();
    convert_stage2();
    __syncthreads();

    for (int s = 0; s < NSTG; s++) {
        if (s + 1 < NSTG) issue_stage(s + 1);
        compute_stage();
        CP_WAIT0();
        __syncthreads();
        if (s + 1 < NSTG) {
            convert_stage2();
            __syncthreads();
        }
    }

    // ---------------- epilogue ----------------
    const int rrow = lid >> 2;            // 0..7
    const int cpair = (lid & 3) * 2;      // even col
    #pragma unroll
    for (int mt = 0; mt < 4; mt++) {
        #pragma unroll
        for (int nt = 0; nt < 2; nt++) {
            int n = n0 + wn * 16 + nt * 8 + cpair;
            if (MODE == 0) {
                #pragma unroll
                for (int hf = 0; hf < 2; hf++) {
                    int m = m0 + wm * 64 + mt * 16 + rrow + hf * 8;
                    float2 st = make_float2(acc[mt][nt][2 * hf], acc[mt][nt][2 * hf + 1]);
                    *(float2*)(D + (size_t)m * EMB + n) = st;
                }
            } else {
                int h  = n >> 7;
                int dd = n & 127;
                float invf = powf(10000.0f, -(float)(dd >> 1) * (1.0f / 64.0f));
                #pragma unroll
                for (int hf = 0; hf < 2; hf++) {
                    int m = m0 + wm * 64 + mt * 16 + rrow + hf * 8;
                    int bb = m >> 11;
                    int sq = m & 2047;
                    float c0 = acc[mt][nt][2 * hf], c1 = acc[mt][nt][2 * hf + 1];
                    float v0 = c0, v1 = c1;
                    if (z < 2) {
                        float ang = (float)sq * invf;
                        float sn, cs;
                        sincosf(ang, &sn, &cs);
                        v0 = c0 * cs - c1 * sn;
                        v1 = c1 * cs + c0 * sn;
                    }
                    float* dst = D + ((size_t)(bb * NHEAD + h) * SEQ + sq) * HDIM + dd;
                    *(float2*)dst = make_float2(v0, v1);
                }
            }
        }
    }
}

// =================================================================================
// Flash attention (fp32, causal). BM=BN=64, D=128, 256 threads. (unchanged, passing)
// =================================================================================
#define FSM_Q   0
#define FSM_K   (128*68)
#define FSM_V   (2*128*68)
#define FSM_P   (2*128*68 + 64*128)
#define FSM_FLT (2*128*68 + 64*128 + 64*68)
#define FSM_BYTES (FSM_FLT * 4)

__global__ void __launch_bounds__(256) flash_kernel(
    const float* __restrict__ Qg, const float* __restrict__ Kg,
    const float* __restrict__ Vg, float* __restrict__ Cg)
{
    extern __shared__ float smf[];
    float* Qs = smf + FSM_Q;
    float* Ks = smf + FSM_K;
    float* Vs = smf + FSM_V;
    float* Ps = smf + FSM_P;

    const int tid = threadIdx.x;
    const int ty = tid >> 4, tx = tid & 15;
    const int q0 = blockIdx.x * 64;
    const int b  = blockIdx.y >> 4, h = blockIdx.y & 15;
    const size_t bh = ((size_t)(b * NHEAD + h)) * SEQ * HDIM;
    const float* Qp = Qg + bh;
    const float* Kp = Kg + bh;
    const float* Vp = Vg + bh;

    const int ml = tid >> 3;
    const int kg = tid & 7;

    #pragma unroll
    for (int mp = 0; mp < 64; mp += 32)
        #pragma unroll
        for (int kp = 0; kp < 32; kp += 8) {
            int m  = ml + mp;
            int k4 = (kg + kp) * 4;
            float4 v = *(const float4*)(Qp + (size_t)(q0 + m) * HDIM + k4);
            Qs[(k4 + 0) * 68 + m] = v.x;
            Qs[(k4 + 1) * 68 + m] = v.y;
            Qs[(k4 + 2) * 68 + m] = v.z;
            Qs[(k4 + 3) * 68 + m] = v.w;
        }

    float o[4][8];
    #pragma unroll
    for (int i = 0; i < 4; i++)
        #pragma unroll
        for (int j = 0; j < 8; j++) o[i][j] = 0.f;
    float mrow[4] = {-1e30f, -1e30f, -1e30f, -1e30f};
    float lrow[4] = {0.f, 0.f, 0.f, 0.f};
    const float scale = 0.08838834764831845f;

    const int nIter = (q0 >> 6) + 1;
    for (int it = 0; it < nIter; it++) {
        const int j0 = it * 64;
        __syncthreads();

        #pragma unroll
        for (int mp = 0; mp < 64; mp += 32)
            #pragma unroll
            for (int kp = 0; kp < 32; kp += 8) {
                int m  = ml + mp;
                int k4 = (kg + kp) * 4;
                float4 v = *(const float4*)(Kp + (size_t)(j0 + m) * HDIM + k4);
                Ks[(k4 + 0) * 68 + m] = v.x;
                Ks[(k4 + 1) * 68 + m] = v.y;
                Ks[(k4 + 2) * 68 + m] = v.z;
                Ks[(k4 + 3) * 68 + m] = v.w;
            }
        #pragma unroll
        for (int i2 = 0; i2 < 8; i2++) {
            int f = tid + 256 * i2;
            int m = f >> 5;
            int d4 = (f & 31) * 4;
            *(float4*)(Vs + m * 128 + d4) =
                *(const float4*)(Vp + (size_t)(j0 + m) * HDIM + d4);
        }
        __syncthreads();

        float s[4][4];
        #pragma unroll
        for (int i = 0; i < 4; i++)
            #pragma unroll
            for (int j = 0; j < 4; j++) s[i][j] = 0.f;

        #pragma unroll 8
        for (int kk = 0; kk < 128; kk++) {
            float4 a  = *(const float4*)(Qs + kk * 68 + ty * 4);
            float4 bv = *(const float4*)(Ks + kk * 68 + tx * 4);
            s[0][0] += a.x * bv.x; s[0][1] += a.x * bv.y; s[0][2] += a.x * bv.z; s[0][3] += a.x * bv.w;
            s[1][0] += a.y * bv.x; s[1][1] += a.y * bv.y; s[1][2] += a.y * bv.z; s[1][3] += a.y * bv.w;
            s[2][0] += a.z * bv.x; s[2][1] += a.z * bv.y; s[2][2] += a.z * bv.z; s[2][3] += a.z * bv.w;
            s[3][0] += a.w * bv.x; s[3][1] += a.w * bv.y; s[3][2] += a.w * bv.z; s[3][3] += a.w * bv.w;
        }

        #pragma unroll
        for (int i = 0; i < 4; i++)
            #pragma unroll
            for (int j = 0; j < 4; j++) {
                float v = s[i][j] * scale;
                if (j0 + tx * 4 + j > q0 + ty * 4 + i) v = -1e30f;
                s[i][j] = v;
            }

        #pragma unroll
        for (int i = 0; i < 4; i++) {
            float mx = fmaxf(fmaxf(s[i][0], s[i][1]), fmaxf(s[i][2], s[i][3]));
            #pragma unroll
            for (int off = 1; off < 16; off <<= 1)
                mx = fmaxf(mx, __shfl_xor_sync(0xffffffffu, mx, off));
            float mnew = fmaxf(mrow[i], mx);
            float corr = expf(mrow[i] - mnew);
            float rsum = 0.f;
            #pragma unroll
            for (int j = 0; j < 4; j++) {
                float p = expf(s[i][j] - mnew);
                s[i][j] = p;
                rsum += p;
            }
            #pragma unroll
            for (int off = 1; off < 16; off <<= 1)
                rsum += __shfl_xor_sync(0xffffffffu, rsum, off);
            lrow[i] = lrow[i] * corr + rsum;
            mrow[i] = mnew;
            #pragma unroll
            for (int j = 0; j < 8; j++) o[i][j] *= corr;
        }

        #pragma unroll
        for (int i = 0; i < 4; i++)
            #pragma unroll
            for (int j = 0; j < 4; j++)
                Ps[(tx * 4 + j) * 68 + ty * 4 + i] = s[i][j];
        __syncthreads();

        #pragma unroll 8
        for (int kk = 0; kk < 64; kk++) {
            float4 p  = *(const float4*)(Ps + kk * 68 + ty * 4);
            float4 v0 = *(const float4*)(Vs + kk * 128 + tx * 8);
            float4 v1 = *(const float4*)(Vs + kk * 128 + tx * 8 + 4);
            o[0][0] += p.x * v0.x; o[0][1] += p.x * v0.y; o[0][2] += p.x * v0.z; o[0][3] += p.x * v0.w;
            o[0][4] += p.x * v1.x; o[0][5] += p.x * v1.y; o[0][6] += p.x * v1.z; o[0][7] += p.x * v1.w;
            o[1][0] += p.y * v0.x; o[1][1] += p.y * v0.y; o[1][2] += p.y * v0.z; o[1][3] += p.y * v0.w;
            o[1][4] += p.y * v1.x; o[1][5] += p.y * v1.y; o[1][6] += p.y * v1.z; o[1][7] += p.y * v1.w;
            o[2][0] += p.z * v0.x; o[2][1] += p.z * v0.y; o[2][2] += p.z * v0.z; o[2][3] += p.z * v0.w;
            o[2][4] += p.z * v1.x; o[2][5] += p.z * v1.y; o[2][6] += p.z * v1.z; o[2][7] += p.z * v1.w;
            o[3][0] += p.w * v0.x; o[3][1] += p.w * v0.y; o[3][2] += p.w * v0.z; o[3][3] += p.w * v0.w;
            o[3][4] += p.w * v1.x; o[3][5] += p.w * v1.y; o[3][6] += p.w * v1.z; o[3][7] += p.w * v1.w;
        }
    }

    #pragma unroll
    for (int i = 0; i < 4; i++) {
        float inv = 1.0f / lrow[i];
        int srow = q0 + ty * 4 + i;
        float* dst = Cg + ((size_t)(b * SEQ + srow)) * EMB + h * HDIM + tx * 8;
        *(float4*)dst       = make_float4(o[i][0] * inv, o[i][1] * inv, o[i][2] * inv, o[i][3] * inv);
        *(float4*)(dst + 4) = make_float4(o[i][4] * inv, o[i][5] * inv, o[i][6] * inv, o[i][7] * inv);
    }
}

// =================================================================================
extern "C" void kernel_launch(void* const* d_in, const int* in_sizes, int n_in,
                              void* d_out, int out_size)
{
    const float* x  = (const float*)d_in[0];
    const float* Wq = (const float*)d_in[1];
    const float* Wk = (const float*)d_in[2];
    const float* Wv = (const float*)d_in[3];
    const float* Wo = (const float*)d_in[4];
    float* out = (float*)d_out;

    float *Q, *K, *V, *C;
    cudaGetSymbolAddress((void**)&Q, g_Q);
    cudaGetSymbolAddress((void**)&K, g_K);
    cudaGetSymbolAddress((void**)&V, g_V);
    cudaGetSymbolAddress((void**)&C, g_C);

    cudaFuncSetAttribute(gemm_mma<1>, cudaFuncAttributeMaxDynamicSharedMemorySize, GSM);
    cudaFuncSetAttribute(gemm_mma<0>, cudaFuncAttributeMaxDynamicSharedMemorySize, GSM);
    cudaFuncSetAttribute(flash_kernel, cudaFuncAttributeMaxDynamicSharedMemorySize, FSM_BYTES);

    // 1) fused QKV projection (fp16x3 mma) + RoPE + [B,H,S,D] transpose
    {
        dim3 grid(EMB / BN, MTOT / BM, 3);
        gemm_mma<1><<<grid, 256, GSM>>>(x, Wq, Wk, Wv, Q, K, V);
    }
    // 2) causal flash attention (fp32)
    {
        dim3 grid(SEQ / 64, BATCH * NHEAD);
        flash_kernel<<<grid, 256, FSM_BYTES>>>(Q, K, V, C);
    }
    // 3) output projection (fp16x3 mma)
    {
        dim3 grid(EMB / BN, MTOT / BM, 1);
        gemm_mma<0><<<grid, 256, GSM>>>(C, Wo, Wo, Wo, out, out, out);
    }
}

// round 4
// speedup vs baseline: 4.0291x; 1.5040x over previous
#include <cuda_runtime.h>
#include <cuda_fp16.h>
#include <math.h>
#include <stdint.h>

#define BATCH  4
#define SEQ    2048
#define EMB    2048
#define NHEAD  16
#define HDIM   128
#define MTOT   (BATCH*SEQ)      // 8192
#define KDIM   2048

// ---------------- scratch (device globals: allocation-free rule) ----------------
__device__ float g_Q[BATCH*NHEAD*SEQ*HDIM];   // [B,H,S,D] after rope
__device__ float g_K[BATCH*NHEAD*SEQ*HDIM];
__device__ float g_V[BATCH*NHEAD*SEQ*HDIM];
__device__ float g_C[BATCH*SEQ*EMB];          // attention context [B,S,E]

__device__ __forceinline__ uint32_t smem_u32(const void* p) {
    uint32_t a;
    asm("{ .reg .u64 t; cvta.to.shared.u64 t, %1; cvt.u32.u64 %0, t; }" : "=r"(a) : "l"(p));
    return a;
}

#define CP_ASYNC16(dst, src) \
    asm volatile("cp.async.cg.shared.global [%0], [%1], 16;" :: "r"(dst), "l"(src))
#define CP_COMMIT() asm volatile("cp.async.commit_group;" ::: "memory")
#define CP_WAIT0()  asm volatile("cp.async.wait_group 0;" ::: "memory")

#define LDMX4(r0,r1,r2,r3, addr) \
    asm volatile("ldmatrix.sync.aligned.m8n8.x4.shared.b16 {%0,%1,%2,%3}, [%4];" \
        : "=r"(r0),"=r"(r1),"=r"(r2),"=r"(r3) : "r"(addr))
#define LDMX4T(r0,r1,r2,r3, addr) \
    asm volatile("ldmatrix.sync.aligned.m8n8.x4.trans.shared.b16 {%0,%1,%2,%3}, [%4];" \
        : "=r"(r0),"=r"(r1),"=r"(r2),"=r"(r3) : "r"(addr))

#define MMA16816(c, a0,a1,a2,a3, b0,b1) \
    asm volatile("mma.sync.aligned.m16n8k16.row.col.f32.f16.f16.f32 " \
        "{%0,%1,%2,%3}, {%4,%5,%6,%7}, {%8,%9}, {%0,%1,%2,%3};" \
        : "+f"((c)[0]),"+f"((c)[1]),"+f"((c)[2]),"+f"((c)[3]) \
        : "r"(a0),"r"(a1),"r"(a2),"r"(a3), "r"(b0),"r"(b1))

__device__ __forceinline__ uint32_t pack_h2(__half x, __half y) {
    __half2 h = __halves2half2(x, y);
    return *(uint32_t*)&h;
}

// =================================================================================
// fp16x3 mma GEMM (unchanged from R3, passing): C[m,n] = sum_k A[m,k]*W[n,k]
// =================================================================================
#define BM 128
#define BN 64
#define BK 64
#define NSTG (KDIM/BK)     // 32

#define SA32 0
#define SB32 32768
#define SAH  49152
#define SAL  65536
#define SBH  81920
#define SBL  90112
#define GSM  98304

template<int MODE>
__global__ void __launch_bounds__(256, 2) gemm_mma(
    const float* __restrict__ A,
    const float* __restrict__ W0, const float* __restrict__ W1, const float* __restrict__ W2,
    float* __restrict__ D0, float* __restrict__ D1, float* __restrict__ D2)
{
    extern __shared__ char sm[];
    const uint32_t sb = smem_u32(sm);

    const float* Bg = W0;
    float* D = D0;
    int z = 0;
    if (MODE == 1) {
        z = blockIdx.z;
        if (z == 1) { Bg = W1; D = D1; }
        else if (z == 2) { Bg = W2; D = D2; }
    }

    const int tid = threadIdx.x;
    const int wid = tid >> 5;
    const int lid = tid & 31;
    const int wm = wid >> 2;
    const int wn = wid & 3;
    const int m0 = blockIdx.y * BM;
    const int n0 = blockIdx.x * BN;

    float acc[4][2][4];
    #pragma unroll
    for (int i = 0; i < 4; i++)
        #pragma unroll
        for (int j = 0; j < 2; j++)
            #pragma unroll
            for (int k = 0; k < 4; k++) acc[i][j][k] = 0.f;

    auto issue_stage = [&](int s) {
        const int kt = s * BK;
        #pragma unroll
        for (int i = 0; i < 8; i++) {
            int idx = i * 256 + tid;
            int r = idx >> 4, c4 = idx & 15;
            CP_ASYNC16(sb + SA32 + r * 256 + c4 * 16,
                       (const char*)(A + (size_t)(m0 + r) * KDIM + kt + c4 * 4));
        }
        #pragma unroll
        for (int i = 0; i < 4; i++) {
            int idx = i * 256 + tid;
            int r = idx >> 4, c4 = idx & 15;
            CP_ASYNC16(sb + SB32 + r * 256 + c4 * 16,
                       (const char*)(Bg + (size_t)(n0 + r) * KDIM + kt + c4 * 4));
        }
        CP_COMMIT();
    };

    auto convert_stage2 = [&]() {
        #pragma unroll
        for (int i = 0; i < 8; i++) {
            int idx = i * 256 + tid;
            int r = idx >> 4, c4 = idx & 15;
            float4 v = *(const float4*)(sm + SA32 + r * 256 + c4 * 16);
            uint32_t off = (uint32_t)(r * 128 + c4 * 8);
            off ^= (off >> 3) & 0x70;
            __half hx = __float2half_rn(v.x), hy = __float2half_rn(v.y);
            __half hz = __float2half_rn(v.z), hw = __float2half_rn(v.w);
            __half lx = __float2half_rn(v.x - __half2float(hx));
            __half ly = __float2half_rn(v.y - __half2float(hy));
            __half lz = __float2half_rn(v.z - __half2float(hz));
            __half lw = __float2half_rn(v.w - __half2float(hw));
            uint2 hp, lp;
            hp.x = pack_h2(hx, hy); hp.y = pack_h2(hz, hw);
            lp.x = pack_h2(lx, ly); lp.y = pack_h2(lz, lw);
            *(uint2*)(sm + SAH + off) = hp;
            *(uint2*)(sm + SAL + off) = lp;
        }
        #pragma unroll
        for (int i = 0; i < 4; i++) {
            int idx = i * 256 + tid;
            int r = idx >> 4, c4 = idx & 15;
            float4 v = *(const float4*)(sm + SB32 + r * 256 + c4 * 16);
            uint32_t off = (uint32_t)(r * 128 + c4 * 8);
            off ^= (off >> 3) & 0x70;
            __half hx = __float2half_rn(v.x), hy = __float2half_rn(v.y);
            __half hz = __float2half_rn(v.z), hw = __float2half_rn(v.w);
            __half lx = __float2half_rn(v.x - __half2float(hx));
            __half ly = __float2half_rn(v.y - __half2float(hy));
            __half lz = __float2half_rn(v.z - __half2float(hz));
            __half lw = __float2half_rn(v.w - __half2float(hw));
            uint2 hp, lp;
            hp.x = pack_h2(hx, hy); hp.y = pack_h2(hz, hw);
            lp.x = pack_h2(lx, ly); lp.y = pack_h2(lz, lw);
            *(uint2*)(sm + SBH + off) = hp;
            *(uint2*)(sm + SBL + off) = lp;
        }
    };

    auto compute_stage = [&]() {
        const int lr = lid & 15;
        const int lc = lid >> 4;
        #pragma unroll
        for (int ks = 0; ks < 4; ks++) {
            uint32_t boff = (uint32_t)((wn * 16 + lr) * 128 + ks * 32 + lc * 16);
            boff ^= (boff >> 3) & 0x70;
            uint32_t bh0, bh1, bh2, bh3, bl0, bl1, bl2, bl3;
            LDMX4(bh0, bh1, bh2, bh3, sb + SBH + boff);
            LDMX4(bl0, bl1, bl2, bl3, sb + SBL + boff);
            #pragma unroll
            for (int mt = 0; mt < 4; mt++) {
                uint32_t aoff = (uint32_t)((wm * 64 + mt * 16 + lr) * 128 + ks * 32 + lc * 16);
                aoff ^= (aoff >> 3) & 0x70;
                uint32_t a0, a1, a2, a3, q0, q1, q2, q3;
                LDMX4(a0, a1, a2, a3, sb + SAH + aoff);
                LDMX4(q0, q1, q2, q3, sb + SAL + aoff);
                MMA16816(acc[mt][0], a0, a1, a2, a3, bh0, bh2);
                MMA16816(acc[mt][0], a0, a1, a2, a3, bl0, bl2);
                MMA16816(acc[mt][0], q0, q1, q2, q3, bh0, bh2);
                MMA16816(acc[mt][1], a0, a1, a2, a3, bh1, bh3);
                MMA16816(acc[mt][1], a0, a1, a2, a3, bl1, bl3);
                MMA16816(acc[mt][1], q0, q1, q2, q3, bh1, bh3);
            }
        }
    };

    issue_stage(0);
    CP_WAIT0();
    __syncthreads();
    convert_stage2();
    __syncthreads();

    for (int s = 0; s < NSTG; s++) {
        if (s + 1 < NSTG) issue_stage(s + 1);
        compute_stage();
        CP_WAIT0();
        __syncthreads();
        if (s + 1 < NSTG) {
            convert_stage2();
            __syncthreads();
        }
    }

    const int rrow = lid >> 2;
    const int cpair = (lid & 3) * 2;
    #pragma unroll
    for (int mt = 0; mt < 4; mt++) {
        #pragma unroll
        for (int nt = 0; nt < 2; nt++) {
            int n = n0 + wn * 16 + nt * 8 + cpair;
            if (MODE == 0) {
                #pragma unroll
                for (int hf = 0; hf < 2; hf++) {
                    int m = m0 + wm * 64 + mt * 16 + rrow + hf * 8;
                    *(float2*)(D + (size_t)m * EMB + n) =
                        make_float2(acc[mt][nt][2 * hf], acc[mt][nt][2 * hf + 1]);
                }
            } else {
                int h  = n >> 7;
                int dd = n & 127;
                float invf = powf(10000.0f, -(float)(dd >> 1) * (1.0f / 64.0f));
                #pragma unroll
                for (int hf = 0; hf < 2; hf++) {
                    int m = m0 + wm * 64 + mt * 16 + rrow + hf * 8;
                    int bb = m >> 11;
                    int sq = m & 2047;
                    float c0 = acc[mt][nt][2 * hf], c1 = acc[mt][nt][2 * hf + 1];
                    float v0 = c0, v1 = c1;
                    if (z < 2) {
                        float ang = (float)sq * invf;
                        float sn, cs;
                        sincosf(ang, &sn, &cs);
                        v0 = c0 * cs - c1 * sn;
                        v1 = c1 * cs + c0 * sn;
                    }
                    float* dst = D + ((size_t)(bb * NHEAD + h) * SEQ + sq) * HDIM + dd;
                    *(float2*)dst = make_float2(v0, v1);
                }
            }
        }
    }
}

// =================================================================================
// Flash attention via mma fp16x3. BM=128 q rows, BN=64 kv per iter, D=128.
// 8 warps, each owns 16 q rows (full row -> intra-quad softmax reductions only).
// P kept in registers (S frag == A frag layout). V via ldmatrix.trans.
// smem (fp16): Kh,Kl [64][128]; Vh,Vl [64][128]; Qh,Ql [128][128]. 128KB.
// =================================================================================
#define FH_KH 0
#define FH_KL 16384
#define FH_VH 32768
#define FH_VL 49152
#define FH_QH 65536
#define FH_QL 98304
#define FH_BYTES 131072

__device__ __forceinline__ uint32_t sw256(uint32_t off) {   // 256B-row swizzle
    return off ^ ((off >> 4) & 0x70);
}

__global__ void __launch_bounds__(256, 1) flash_mma(
    const float* __restrict__ Qg, const float* __restrict__ Kg,
    const float* __restrict__ Vg, float* __restrict__ Cg)
{
    extern __shared__ char sm[];
    const uint32_t sb = smem_u32(sm);

    const int tid = threadIdx.x;
    const int wid = tid >> 5;
    const int lid = tid & 31;
    // longest CTAs (largest q0) first
    const int q0 = (gridDim.x - 1 - blockIdx.x) * 128;
    const int b  = blockIdx.y >> 4, h = blockIdx.y & 15;
    const size_t bh = ((size_t)(b * NHEAD + h)) * SEQ * HDIM;
    const float* Qp = Qg + bh;
    const float* Kp = Kg + bh;
    const float* Vp = Vg + bh;

    // ---- load Q once: hi/lo fp16, swizzled [128][128] ----
    {
        const int row = tid >> 1;
        const int ch  = (tid & 1) * 64;
        const float* src = Qp + (size_t)(q0 + row) * HDIM + ch;
        #pragma unroll
        for (int c = 0; c < 16; c++) {
            float4 v = *(const float4*)(src + c * 4);
            uint32_t off = sw256((uint32_t)(row * 256 + (ch + c * 4) * 2));
            __half hx = __float2half_rn(v.x), hy = __float2half_rn(v.y);
            __half hz = __float2half_rn(v.z), hw = __float2half_rn(v.w);
            uint2 hp, lp;
            hp.x = pack_h2(hx, hy); hp.y = pack_h2(hz, hw);
            lp.x = pack_h2(__float2half_rn(v.x - __half2float(hx)),
                           __float2half_rn(v.y - __half2float(hy)));
            lp.y = pack_h2(__float2half_rn(v.z - __half2float(hz)),
                           __float2half_rn(v.w - __half2float(hw)));
            *(uint2*)(sm + FH_QH + off) = hp;
            *(uint2*)(sm + FH_QL + off) = lp;
        }
    }

    float os[16][4];
    #pragma unroll
    for (int i = 0; i < 16; i++)
        #pragma unroll
        for (int j = 0; j < 4; j++) os[i][j] = 0.f;
    float mrow[2] = {-1e30f, -1e30f};
    float lrow[2] = {0.f, 0.f};
    const float scale = 0.08838834764831845f;   // 1/sqrt(128)

    const int lr = lid & 15;
    const int lc = lid >> 4;

    const int nIter = (q0 >> 6) + 2;
    for (int it = 0; it < nIter; it++) {
        const int j0 = it * 64;
        __syncthreads();

        // ---- load K,V tile: hi/lo fp16, swizzled ----
        {
            const int row = tid >> 2;
            const int cq  = (tid & 3) * 32;
            const float* ksrc = Kp + (size_t)(j0 + row) * HDIM + cq;
            const float* vsrc = Vp + (size_t)(j0 + row) * HDIM + cq;
            #pragma unroll
            for (int c = 0; c < 8; c++) {
                uint32_t off = sw256((uint32_t)(row * 256 + (cq + c * 4) * 2));
                float4 v = *(const float4*)(ksrc + c * 4);
                __half hx = __float2half_rn(v.x), hy = __float2half_rn(v.y);
                __half hz = __float2half_rn(v.z), hw = __float2half_rn(v.w);
                uint2 hp, lp;
                hp.x = pack_h2(hx, hy); hp.y = pack_h2(hz, hw);
                lp.x = pack_h2(__float2half_rn(v.x - __half2float(hx)),
                               __float2half_rn(v.y - __half2float(hy)));
                lp.y = pack_h2(__float2half_rn(v.z - __half2float(hz)),
                               __float2half_rn(v.w - __half2float(hw)));
                *(uint2*)(sm + FH_KH + off) = hp;
                *(uint2*)(sm + FH_KL + off) = lp;

                v = *(const float4*)(vsrc + c * 4);
                hx = __float2half_rn(v.x); hy = __float2half_rn(v.y);
                hz = __float2half_rn(v.z); hw = __float2half_rn(v.w);
                hp.x = pack_h2(hx, hy); hp.y = pack_h2(hz, hw);
                lp.x = pack_h2(__float2half_rn(v.x - __half2float(hx)),
                               __float2half_rn(v.y - __half2float(hy)));
                lp.y = pack_h2(__float2half_rn(v.z - __half2float(hz)),
                               __float2half_rn(v.w - __half2float(hw)));
                *(uint2*)(sm + FH_VH + off) = hp;
                *(uint2*)(sm + FH_VL + off) = lp;
            }
        }
        __syncthreads();

        // fully-masked warp tile? (min col j0 > max row of this warp)
        if (j0 >= q0 + (wid + 1) * 16) continue;

        // ---- S = Q K^T (3-pass hi/lo) ----
        float sacc[8][4];
        #pragma unroll
        for (int i = 0; i < 8; i++)
            #pragma unroll
            for (int j = 0; j < 4; j++) sacc[i][j] = 0.f;

        #pragma unroll
        for (int ks = 0; ks < 8; ks++) {
            uint32_t aoff = sw256((uint32_t)((wid * 16 + lr) * 256 + ks * 32 + lc * 16));
            uint32_t qh0, qh1, qh2, qh3, ql0, ql1, ql2, ql3;
            LDMX4(qh0, qh1, qh2, qh3, sb + FH_QH + aoff);
            LDMX4(ql0, ql1, ql2, ql3, sb + FH_QL + aoff);
            #pragma unroll
            for (int bg = 0; bg < 4; bg++) {
                uint32_t boff = sw256((uint32_t)((bg * 16 + lr) * 256 + ks * 32 + lc * 16));
                uint32_t kh0, kh1, kh2, kh3, kl0, kl1, kl2, kl3;
                LDMX4(kh0, kh1, kh2, kh3, sb + FH_KH + boff);
                LDMX4(kl0, kl1, kl2, kl3, sb + FH_KL + boff);
                MMA16816(sacc[bg * 2],     qh0, qh1, qh2, qh3, kh0, kh2);
                MMA16816(sacc[bg * 2],     qh0, qh1, qh2, qh3, kl0, kl2);
                MMA16816(sacc[bg * 2],     ql0, ql1, ql2, ql3, kh0, kh2);
                MMA16816(sacc[bg * 2 + 1], qh0, qh1, qh2, qh3, kh1, kh3);
                MMA16816(sacc[bg * 2 + 1], qh0, qh1, qh2, qh3, kl1, kl3);
                MMA16816(sacc[bg * 2 + 1], ql0, ql1, ql2, ql3, kh1, kh3);
            }
        }

        // ---- scale + causal mask ----
        const int r0g = q0 + wid * 16 + (lid >> 2);
        const int c0g = j0 + 2 * (lid & 3);
        #pragma unroll
        for (int nt = 0; nt < 8; nt++)
            #pragma unroll
            for (int c = 0; c < 4; c++) {
                int rr = r0g + ((c >= 2) ? 8 : 0);
                int cc = c0g + nt * 8 + (c & 1);
                float v = sacc[nt][c] * scale;
                if (cc > rr) v = -1e30f;
                sacc[nt][c] = v;
            }

        // ---- online softmax (rows: c0,c1 -> row0; c2,c3 -> row1) ----
        float mx0 = -1e30f, mx1 = -1e30f;
        #pragma unroll
        for (int nt = 0; nt < 8; nt++) {
            mx0 = fmaxf(mx0, fmaxf(sacc[nt][0], sacc[nt][1]));
            mx1 = fmaxf(mx1, fmaxf(sacc[nt][2], sacc[nt][3]));
        }
        #pragma unroll
        for (int o = 1; o < 4; o <<= 1) {
            mx0 = fmaxf(mx0, __shfl_xor_sync(0xffffffffu, mx0, o));
            mx1 = fmaxf(mx1, __shfl_xor_sync(0xffffffffu, mx1, o));
        }
        float mn0 = fmaxf(mrow[0], mx0);
        float mn1 = fmaxf(mrow[1], mx1);
        float cr0 = __expf(mrow[0] - mn0);
        float cr1 = __expf(mrow[1] - mn1);
        float rs0 = 0.f, rs1 = 0.f;
        #pragma unroll
        for (int nt = 0; nt < 8; nt++) {
            float p0 = __expf(sacc[nt][0] - mn0);
            float p1 = __expf(sacc[nt][1] - mn0);
            float p2 = __expf(sacc[nt][2] - mn1);
            float p3 = __expf(sacc[nt][3] - mn1);
            sacc[nt][0] = p0; sacc[nt][1] = p1; sacc[nt][2] = p2; sacc[nt][3] = p3;
            rs0 += p0 + p1; rs1 += p2 + p3;
        }
        #pragma unroll
        for (int o = 1; o < 4; o <<= 1) {
            rs0 += __shfl_xor_sync(0xffffffffu, rs0, o);
            rs1 += __shfl_xor_sync(0xffffffffu, rs1, o);
        }
        lrow[0] = lrow[0] * cr0 + rs0;
        lrow[1] = lrow[1] * cr1 + rs1;
        mrow[0] = mn0; mrow[1] = mn1;
        #pragma unroll
        for (int nt = 0; nt < 16; nt++) {
            os[nt][0] *= cr0; os[nt][1] *= cr0;
            os[nt][2] *= cr1; os[nt][3] *= cr1;
        }

        // ---- O += P V (P in registers, 3-pass) ----
        #pragma unroll
        for (int kt = 0; kt < 4; kt++) {
            uint32_t ah[4], al[4];
            #pragma unroll
            for (int q = 0; q < 4; q++) {
                int nt = 2 * kt + (q >> 1);
                int cc = (q & 1) * 2;
                float x = sacc[nt][cc], y = sacc[nt][cc + 1];
                __half hx = __float2half_rn(x), hy = __float2half_rn(y);
                ah[q] = pack_h2(hx, hy);
                al[q] = pack_h2(__float2half_rn(x - __half2float(hx)),
                                __float2half_rn(y - __half2float(hy)));
            }
            const int vrow = kt * 16 + (lid & 7) + ((lid >> 3) & 1) * 8;
            const int vnh  = (lid >> 4) * 8;
            #pragma unroll
            for (int bg2 = 0; bg2 < 8; bg2++) {
                uint32_t voff = sw256((uint32_t)(vrow * 256 + (bg2 * 16 + vnh) * 2));
                uint32_t vh0, vh1, vh2, vh3, vl0, vl1, vl2, vl3;
                LDMX4T(vh0, vh1, vh2, vh3, sb + FH_VH + voff);
                LDMX4T(vl0, vl1, vl2, vl3, sb + FH_VL + voff);
                MMA16816(os[bg2 * 2],     ah[0], ah[1], ah[2], ah[3], vh0, vh1);
                MMA16816(os[bg2 * 2],     ah[0], ah[1], ah[2], ah[3], vl0, vl1);
                MMA16816(os[bg2 * 2],     al[0], al[1], al[2], al[3], vh0, vh1);
                MMA16816(os[bg2 * 2 + 1], ah[0], ah[1], ah[2], ah[3], vh2, vh3);
                MMA16816(os[bg2 * 2 + 1], ah[0], ah[1], ah[2], ah[3], vl2, vl3);
                MMA16816(os[bg2 * 2 + 1], al[0], al[1], al[2], al[3], vh2, vh3);
            }
        }
    }

    // ---- epilogue: ctx[b, s, h*128 + d] ----
    const float inv0 = 1.0f / lrow[0];
    const float inv1 = 1.0f / lrow[1];
    const int row0 = q0 + wid * 16 + (lid >> 2);
    const int dbase = 2 * (lid & 3);
    #pragma unroll
    for (int nt = 0; nt < 16; nt++) {
        int d = nt * 8 + dbase;
        float* dst0 = Cg + ((size_t)(b * SEQ + row0))     * EMB + h * HDIM + d;
        float* dst1 = Cg + ((size_t)(b * SEQ + row0 + 8)) * EMB + h * HDIM + d;
        *(float2*)dst0 = make_float2(os[nt][0] * inv0, os[nt][1] * inv0);
        *(float2*)dst1 = make_float2(os[nt][2] * inv1, os[nt][3] * inv1);
    }
}

// =================================================================================
extern "C" void kernel_launch(void* const* d_in, const int* in_sizes, int n_in,
                              void* d_out, int out_size)
{
    const float* x  = (const float*)d_in[0];
    const float* Wq = (const float*)d_in[1];
    const float* Wk = (const float*)d_in[2];
    const float* Wv = (const float*)d_in[3];
    const float* Wo = (const float*)d_in[4];
    float* out = (float*)d_out;

    float *Q, *K, *V, *C;
    cudaGetSymbolAddress((void**)&Q, g_Q);
    cudaGetSymbolAddress((void**)&K, g_K);
    cudaGetSymbolAddress((void**)&V, g_V);
    cudaGetSymbolAddress((void**)&C, g_C);

    cudaFuncSetAttribute(gemm_mma<1>, cudaFuncAttributeMaxDynamicSharedMemorySize, GSM);
    cudaFuncSetAttribute(gemm_mma<0>, cudaFuncAttributeMaxDynamicSharedMemorySize, GSM);
    cudaFuncSetAttribute(flash_mma, cudaFuncAttributeMaxDynamicSharedMemorySize, FH_BYTES);

    // 1) fused QKV projection (fp16x3 mma) + RoPE + [B,H,S,D] transpose
    {
        dim3 grid(EMB / BN, MTOT / BM, 3);
        gemm_mma<1><<<grid, 256, GSM>>>(x, Wq, Wk, Wv, Q, K, V);
    }
    // 2) causal flash attention (fp16x3 mma)
    {
        dim3 grid(SEQ / 128, BATCH * NHEAD);
        flash_mma<<<grid, 256, FH_BYTES>>>(Q, K, V, C);
    }
    // 3) output projection (fp16x3 mma)
    {
        dim3 grid(EMB / BN, MTOT / BM, 1);
        gemm_mma<0><<<grid, 256, GSM>>>(C, Wo, Wo, Wo, out, out, out);
    }
}

// round 5
// speedup vs baseline: 5.3674x; 1.3322x over previous
#include <cuda_runtime.h>
#include <cuda_fp16.h>
#include <math.h>
#include <stdint.h>

#define BATCH  4
#define SEQ    2048
#define EMB    2048
#define NHEAD  16
#define HDIM   128
#define MTOT   (BATCH*SEQ)      // 8192
#define KDIM   2048
#define NELEM_X (MTOT*KDIM)     // 16.8M
#define NELEM_W (KDIM*KDIM)     // 4.19M

// ---------------- scratch (device globals: allocation-free rule) ----------------
__device__ __half g_xh[NELEM_X],  g_xl[NELEM_X];
__device__ __half g_Wh[4][NELEM_W], g_Wl[4][NELEM_W];
__device__ __half g_Qh[NELEM_X], g_Ql[NELEM_X];
__device__ __half g_Kh[NELEM_X], g_Kl[NELEM_X];
__device__ __half g_Vh[NELEM_X], g_Vl[NELEM_X];
__device__ __half g_Ch[NELEM_X], g_Cl[NELEM_X];

__device__ __forceinline__ uint32_t smem_u32(const void* p) {
    uint32_t a;
    asm("{ .reg .u64 t; cvta.to.shared.u64 t, %1; cvt.u32.u64 %0, t; }" : "=r"(a) : "l"(p));
    return a;
}

#define CP_ASYNC16(dst, src) \
    asm volatile("cp.async.cg.shared.global [%0], [%1], 16;" :: "r"(dst), "l"(src))
#define CP_COMMIT() asm volatile("cp.async.commit_group;" ::: "memory")
#define CP_WAIT(n)  asm volatile("cp.async.wait_group %0;" :: "n"(n) : "memory")

#define LDMX4(r0,r1,r2,r3, addr) \
    asm volatile("ldmatrix.sync.aligned.m8n8.x4.shared.b16 {%0,%1,%2,%3}, [%4];" \
        : "=r"(r0),"=r"(r1),"=r"(r2),"=r"(r3) : "r"(addr))
#define LDMX4T(r0,r1,r2,r3, addr) \
    asm volatile("ldmatrix.sync.aligned.m8n8.x4.trans.shared.b16 {%0,%1,%2,%3}, [%4];" \
        : "=r"(r0),"=r"(r1),"=r"(r2),"=r"(r3) : "r"(addr))

#define MMA16816(c, a0,a1,a2,a3, b0,b1) \
    asm volatile("mma.sync.aligned.m16n8k16.row.col.f32.f16.f16.f32 " \
        "{%0,%1,%2,%3}, {%4,%5,%6,%7}, {%8,%9}, {%0,%1,%2,%3};" \
        : "+f"((c)[0]),"+f"((c)[1]),"+f"((c)[2]),"+f"((c)[3]) \
        : "r"(a0),"r"(a1),"r"(a2),"r"(a3), "r"(b0),"r"(b1))

__device__ __forceinline__ uint32_t pack_h2(__half x, __half y) {
    __half2 h = __halves2half2(x, y);
    return *(uint32_t*)&h;
}
__device__ __forceinline__ void split_hl(float x, float y, uint32_t& hp, uint32_t& lp) {
    __half hx = __float2half_rn(x), hy = __float2half_rn(y);
    hp = pack_h2(hx, hy);
    lp = pack_h2(__float2half_rn(x - __half2float(hx)),
                 __float2half_rn(y - __half2float(hy)));
}

// =================================================================================
// pre-convert: fp32 -> fp16 hi/lo (elementwise, vectorized x4)
// =================================================================================
__global__ void __launch_bounds__(256) conv_hl(
    const float* __restrict__ s, __half* __restrict__ h, __half* __restrict__ l)
{
    int i = blockIdx.x * 256 + threadIdx.x;
    float4 v = ((const float4*)s)[i];
    uint2 hp, lp;
    split_hl(v.x, v.y, hp.x, lp.x);
    split_hl(v.z, v.w, hp.y, lp.y);
    ((uint2*)h)[i] = hp;
    ((uint2*)l)[i] = lp;
}

// =================================================================================
// fp16x3 mma GEMM on pre-converted inputs: C[m,n] = sum_k A[m,k]*W[n,k]
// BM=128, BN=64, BK=64; 8 warps 2x4; 2-stage cp.async double buffer; no convert.
// MODE 0: plain fp32 store.  MODE 1: QKV (z), RoPE for z<2, hi/lo fp16 [B,H,S,D].
// =================================================================================
#define BM 128
#define BN 64
#define BK 64
#define NSTG (KDIM/BK)     // 32

// per-stage smem layout (bytes): Ah 16K | Al 16K | Bh 8K | Bl 8K  = 48K
#define GS_AH 0
#define GS_AL 16384
#define GS_BH 32768
#define GS_BL 40960
#define GS_STRIDE 49152
#define GSM (2*GS_STRIDE)   // 96KB

template<int MODE>
__global__ void __launch_bounds__(256, 2) gemm_hl(
    const __half* __restrict__ Ah, const __half* __restrict__ Al,
    const __half* __restrict__ Bh0, const __half* __restrict__ Bl0,
    const __half* __restrict__ Bh1, const __half* __restrict__ Bl1,
    const __half* __restrict__ Bh2, const __half* __restrict__ Bl2,
    __half* __restrict__ Dh0, __half* __restrict__ Dl0,
    __half* __restrict__ Dh1, __half* __restrict__ Dl1,
    __half* __restrict__ Dh2, __half* __restrict__ Dl2,
    float* __restrict__ Dout)
{
    extern __shared__ char sm[];
    const uint32_t sb = smem_u32(sm);

    const __half* Bh = Bh0;
    const __half* Bl = Bl0;
    int z = 0;
    if (MODE == 1) {
        z = blockIdx.z;
        if (z == 1) { Bh = Bh1; Bl = Bl1; }
        else if (z == 2) { Bh = Bh2; Bl = Bl2; }
    }

    const int tid = threadIdx.x;
    const int wid = tid >> 5;
    const int lid = tid & 31;
    const int wm = wid >> 2;
    const int wn = wid & 3;
    const int m0 = blockIdx.y * BM;
    const int n0 = blockIdx.x * BN;

    float acc[4][2][4];
    #pragma unroll
    for (int i = 0; i < 4; i++)
        #pragma unroll
        for (int j = 0; j < 2; j++)
            #pragma unroll
            for (int k = 0; k < 4; k++) acc[i][j][k] = 0.f;

    // cp.async issue for stage s into buffer (s&1). 12 chunks / thread.
    auto issue_stage = [&](int s) {
        const int kt = s * BK;
        const uint32_t base = sb + (s & 1) * GS_STRIDE;
        // A: 128 rows x 128B (hi, lo): 1024 chunks each
        #pragma unroll
        for (int i = 0; i < 4; i++) {
            int c = i * 256 + tid;
            int r = c >> 3, c16 = c & 7;
            uint32_t off = (uint32_t)(r * 128 + c16 * 16);
            off ^= (off >> 3) & 0x70;
            const __half* srcH = Ah + (size_t)(m0 + r) * KDIM + kt + c16 * 8;
            const __half* srcL = Al + (size_t)(m0 + r) * KDIM + kt + c16 * 8;
            CP_ASYNC16(base + GS_AH + off, srcH);
            CP_ASYNC16(base + GS_AL + off, srcL);
        }
        // B: 64 rows x 128B (hi, lo): 512 chunks each
        #pragma unroll
        for (int i = 0; i < 2; i++) {
            int c = i * 256 + tid;
            int r = c >> 3, c16 = c & 7;
            uint32_t off = (uint32_t)(r * 128 + c16 * 16);
            off ^= (off >> 3) & 0x70;
            const __half* srcH = Bh + (size_t)(n0 + r) * KDIM + kt + c16 * 8;
            const __half* srcL = Bl + (size_t)(n0 + r) * KDIM + kt + c16 * 8;
            CP_ASYNC16(base + GS_BH + off, srcH);
            CP_ASYNC16(base + GS_BL + off, srcL);
        }
        CP_COMMIT();
    };

    auto compute_stage = [&](int s) {
        const uint32_t base = sb + (s & 1) * GS_STRIDE;
        const int lr = lid & 15;
        const int lc = lid >> 4;
        #pragma unroll
        for (int ks = 0; ks < 4; ks++) {
            uint32_t boff = (uint32_t)((wn * 16 + lr) * 128 + ks * 32 + lc * 16);
            boff ^= (boff >> 3) & 0x70;
            uint32_t bh0, bh1, bh2, bh3, bl0, bl1, bl2, bl3;
            LDMX4(bh0, bh1, bh2, bh3, base + GS_BH + boff);
            LDMX4(bl0, bl1, bl2, bl3, base + GS_BL + boff);
            #pragma unroll
            for (int mt = 0; mt < 4; mt++) {
                uint32_t aoff = (uint32_t)((wm * 64 + mt * 16 + lr) * 128 + ks * 32 + lc * 16);
                aoff ^= (aoff >> 3) & 0x70;
                uint32_t a0, a1, a2, a3, q0, q1, q2, q3;
                LDMX4(a0, a1, a2, a3, base + GS_AH + aoff);
                LDMX4(q0, q1, q2, q3, base + GS_AL + aoff);
                MMA16816(acc[mt][0], a0, a1, a2, a3, bh0, bh2);
                MMA16816(acc[mt][0], a0, a1, a2, a3, bl0, bl2);
                MMA16816(acc[mt][0], q0, q1, q2, q3, bh0, bh2);
                MMA16816(acc[mt][1], a0, a1, a2, a3, bh1, bh3);
                MMA16816(acc[mt][1], a0, a1, a2, a3, bl1, bl3);
                MMA16816(acc[mt][1], q0, q1, q2, q3, bh1, bh3);
            }
        }
    };

    issue_stage(0);
    for (int s = 0; s < NSTG; s++) {
        if (s + 1 < NSTG) {
            issue_stage(s + 1);
            CP_WAIT(1);
        } else {
            CP_WAIT(0);
        }
        __syncthreads();      // stage s data visible to all
        compute_stage(s);
        __syncthreads();      // all warps done before buffer reuse (stage s+2 issue)
    }

    // ---------------- epilogue ----------------
    const int rrow = lid >> 2;
    const int cpair = (lid & 3) * 2;
    #pragma unroll
    for (int mt = 0; mt < 4; mt++) {
        #pragma unroll
        for (int nt = 0; nt < 2; nt++) {
            int n = n0 + wn * 16 + nt * 8 + cpair;
            if (MODE == 0) {
                #pragma unroll
                for (int hf = 0; hf < 2; hf++) {
                    int m = m0 + wm * 64 + mt * 16 + rrow + hf * 8;
                    *(float2*)(Dout + (size_t)m * EMB + n) =
                        make_float2(acc[mt][nt][2 * hf], acc[mt][nt][2 * hf + 1]);
                }
            } else {
                __half* Dh = (z == 0) ? Dh0 : (z == 1) ? Dh1 : Dh2;
                __half* Dl = (z == 0) ? Dl0 : (z == 1) ? Dl1 : Dl2;
                int h  = n >> 7;
                int dd = n & 127;
                float invf = powf(10000.0f, -(float)(dd >> 1) * (1.0f / 64.0f));
                #pragma unroll
                for (int hf = 0; hf < 2; hf++) {
                    int m = m0 + wm * 64 + mt * 16 + rrow + hf * 8;
                    int bb = m >> 11;
                    int sq = m & 2047;
                    float c0 = acc[mt][nt][2 * hf], c1 = acc[mt][nt][2 * hf + 1];
                    float v0 = c0, v1 = c1;
                    if (z < 2) {
                        float ang = (float)sq * invf;
                        float sn, cs;
                        sincosf(ang, &sn, &cs);
                        v0 = c0 * cs - c1 * sn;
                        v1 = c1 * cs + c0 * sn;
                    }
                    size_t idx = ((size_t)(bb * NHEAD + h) * SEQ + sq) * HDIM + dd;
                    uint32_t hp, lp;
                    split_hl(v0, v1, hp, lp);
                    *(uint32_t*)(Dh + idx) = hp;
                    *(uint32_t*)(Dl + idx) = lp;
                }
            }
        }
    }
}

// =================================================================================
// Flash attention, fp16x3 mma, pre-converted hi/lo inputs, K/V double-buffered.
// BM=128 q rows, BN=64 kv per iter, D=128, 8 warps (16 rows each).
// smem: Qh 32K | Ql 32K | 2 x (Kh 16K | Kl 16K | Vh 16K | Vl 16K) = 192KB
// =================================================================================
#define FQH 0
#define FQL 32768
#define FKV 65536
#define FKV_STRIDE 65536
#define FKH 0
#define FKL 16384
#define FVH 32768
#define FVL 49152
#define FH_BYTES 196608

__device__ __forceinline__ uint32_t sw256(uint32_t off) {
    return off ^ ((off >> 4) & 0x70);
}

__global__ void __launch_bounds__(256, 1) flash_mma(
    const __half* __restrict__ Qh, const __half* __restrict__ Ql,
    const __half* __restrict__ Kh, const __half* __restrict__ Kl,
    const __half* __restrict__ Vh, const __half* __restrict__ Vl,
    __half* __restrict__ Ch, __half* __restrict__ Cl)
{
    extern __shared__ char sm[];
    const uint32_t sb = smem_u32(sm);

    const int tid = threadIdx.x;
    const int wid = tid >> 5;
    const int lid = tid & 31;
    const int q0 = (gridDim.x - 1 - blockIdx.x) * 128;   // longest first
    const int b  = blockIdx.y >> 4, h = blockIdx.y & 15;
    const size_t bh = ((size_t)(b * NHEAD + h)) * SEQ * HDIM;

    const int nIter = (q0 >> 6) + 2;

    // ---- issue Q (once) + KV stage 0, one commit group ----
    auto issue_kv = [&](int it, int buf) {
        const int j0 = it * 64;
        const uint32_t base = sb + FKV + buf * FKV_STRIDE;
        #pragma unroll
        for (int i = 0; i < 4; i++) {
            int c = i * 256 + tid;              // 1024 chunks per array
            int r = c >> 4, c16 = c & 15;
            uint32_t off = sw256((uint32_t)(r * 256 + c16 * 16));
            size_t src = bh + (size_t)(j0 + r) * HDIM + c16 * 8;
            CP_ASYNC16(base + FKH + off, Kh + src);
            CP_ASYNC16(base + FKL + off, Kl + src);
            CP_ASYNC16(base + FVH + off, Vh + src);
            CP_ASYNC16(base + FVL + off, Vl + src);
        }
        CP_COMMIT();
    };

    {   // Q: 128 rows x 256B, hi+lo: 2048 chunks each
        #pragma unroll
        for (int i = 0; i < 8; i++) {
            int c = i * 256 + tid;
            int r = c >> 4, c16 = c & 15;
            uint32_t off = sw256((uint32_t)(r * 256 + c16 * 16));
            size_t src = bh + (size_t)(q0 + r) * HDIM + c16 * 8;
            CP_ASYNC16(sb + FQH + off, Qh + src);
            CP_ASYNC16(sb + FQL + off, Ql + src);
        }
    }
    issue_kv(0, 0);   // commits Q + KV0 together

    float os[16][4];
    #pragma unroll
    for (int i = 0; i < 16; i++)
        #pragma unroll
        for (int j = 0; j < 4; j++) os[i][j] = 0.f;
    float mrow[2] = {-1e30f, -1e30f};
    float lrow[2] = {0.f, 0.f};
    const float scale = 0.08838834764831845f;

    const int lr = lid & 15;
    const int lc = lid >> 4;

    for (int it = 0; it < nIter; it++) {
        const int j0 = it * 64;
        const int buf = it & 1;
        const uint32_t kbase = sb + FKV + buf * FKV_STRIDE;

        if (it + 1 < nIter) {
            issue_kv(it + 1, buf ^ 1);
            CP_WAIT(1);
        } else {
            CP_WAIT(0);
        }
        __syncthreads();

        if (j0 < q0 + (wid + 1) * 16) {     // warp has unmasked work
            // ---- S = Q K^T (3-pass) ----
            float sacc[8][4];
            #pragma unroll
            for (int i = 0; i < 8; i++)
                #pragma unroll
                for (int j = 0; j < 4; j++) sacc[i][j] = 0.f;

            #pragma unroll
            for (int ks = 0; ks < 8; ks++) {
                uint32_t aoff = sw256((uint32_t)((wid * 16 + lr) * 256 + ks * 32 + lc * 16));
                uint32_t qh0, qh1, qh2, qh3, ql0, ql1, ql2, ql3;
                LDMX4(qh0, qh1, qh2, qh3, sb + FQH + aoff);
                LDMX4(ql0, ql1, ql2, ql3, sb + FQL + aoff);
                #pragma unroll
                for (int bg = 0; bg < 4; bg++) {
                    uint32_t boff = sw256((uint32_t)((bg * 16 + lr) * 256 + ks * 32 + lc * 16));
                    uint32_t kh0, kh1, kh2, kh3, kl0, kl1, kl2, kl3;
                    LDMX4(kh0, kh1, kh2, kh3, kbase + FKH + boff);
                    LDMX4(kl0, kl1, kl2, kl3, kbase + FKL + boff);
                    MMA16816(sacc[bg * 2],     qh0, qh1, qh2, qh3, kh0, kh2);
                    MMA16816(sacc[bg * 2],     qh0, qh1, qh2, qh3, kl0, kl2);
                    MMA16816(sacc[bg * 2],     ql0, ql1, ql2, ql3, kh0, kh2);
                    MMA16816(sacc[bg * 2 + 1], qh0, qh1, qh2, qh3, kh1, kh3);
                    MMA16816(sacc[bg * 2 + 1], qh0, qh1, qh2, qh3, kl1, kl3);
                    MMA16816(sacc[bg * 2 + 1], ql0, ql1, ql2, ql3, kh1, kh3);
                }
            }

            // ---- scale + causal mask ----
            const int r0g = q0 + wid * 16 + (lid >> 2);
            const int c0g = j0 + 2 * (lid & 3);
            #pragma unroll
            for (int nt = 0; nt < 8; nt++)
                #pragma unroll
                for (int c = 0; c < 4; c++) {
                    int rr = r0g + ((c >= 2) ? 8 : 0);
                    int cc = c0g + nt * 8 + (c & 1);
                    float v = sacc[nt][c] * scale;
                    if (cc > rr) v = -1e30f;
                    sacc[nt][c] = v;
                }

            // ---- online softmax ----
            float mx0 = -1e30f, mx1 = -1e30f;
            #pragma unroll
            for (int nt = 0; nt < 8; nt++) {
                mx0 = fmaxf(mx0, fmaxf(sacc[nt][0], sacc[nt][1]));
                mx1 = fmaxf(mx1, fmaxf(sacc[nt][2], sacc[nt][3]));
            }
            #pragma unroll
            for (int o = 1; o < 4; o <<= 1) {
                mx0 = fmaxf(mx0, __shfl_xor_sync(0xffffffffu, mx0, o));
                mx1 = fmaxf(mx1, __shfl_xor_sync(0xffffffffu, mx1, o));
            }
            float mn0 = fmaxf(mrow[0], mx0);
            float mn1 = fmaxf(mrow[1], mx1);
            float cr0 = __expf(mrow[0] - mn0);
            float cr1 = __expf(mrow[1] - mn1);
            float rs0 = 0.f, rs1 = 0.f;
            #pragma unroll
            for (int nt = 0; nt < 8; nt++) {
                float p0 = __expf(sacc[nt][0] - mn0);
                float p1 = __expf(sacc[nt][1] - mn0);
                float p2 = __expf(sacc[nt][2] - mn1);
                float p3 = __expf(sacc[nt][3] - mn1);
                sacc[nt][0] = p0; sacc[nt][1] = p1; sacc[nt][2] = p2; sacc[nt][3] = p3;
                rs0 += p0 + p1; rs1 += p2 + p3;
            }
            #pragma unroll
            for (int o = 1; o < 4; o <<= 1) {
                rs0 += __shfl_xor_sync(0xffffffffu, rs0, o);
                rs1 += __shfl_xor_sync(0xffffffffu, rs1, o);
            }
            lrow[0] = lrow[0] * cr0 + rs0;
            lrow[1] = lrow[1] * cr1 + rs1;
            mrow[0] = mn0; mrow[1] = mn1;
            #pragma unroll
            for (int nt = 0; nt < 16; nt++) {
                os[nt][0] *= cr0; os[nt][1] *= cr0;
                os[nt][2] *= cr1; os[nt][3] *= cr1;
            }

            // ---- O += P V ----
            #pragma unroll
            for (int kt = 0; kt < 4; kt++) {
                uint32_t ah[4], al[4];
                #pragma unroll
                for (int q = 0; q < 4; q++) {
                    int nt = 2 * kt + (q >> 1);
                    int cc = (q & 1) * 2;
                    split_hl(sacc[nt][cc], sacc[nt][cc + 1], ah[q], al[q]);
                }
                const int vrow = kt * 16 + (lid & 7) + ((lid >> 3) & 1) * 8;
                const int vnh  = (lid >> 4) * 8;
                #pragma unroll
                for (int bg2 = 0; bg2 < 8; bg2++) {
                    uint32_t voff = sw256((uint32_t)(vrow * 256 + (bg2 * 16 + vnh) * 2));
                    uint32_t vh0, vh1, vh2, vh3, vl0, vl1, vl2, vl3;
                    LDMX4T(vh0, vh1, vh2, vh3, kbase + FVH + voff);
                    LDMX4T(vl0, vl1, vl2, vl3, kbase + FVL + voff);
                    MMA16816(os[bg2 * 2],     ah[0], ah[1], ah[2], ah[3], vh0, vh1);
                    MMA16816(os[bg2 * 2],     ah[0], ah[1], ah[2], ah[3], vl0, vl1);
                    MMA16816(os[bg2 * 2],     al[0], al[1], al[2], al[3], vh0, vh1);
                    MMA16816(os[bg2 * 2 + 1], ah[0], ah[1], ah[2], ah[3], vh2, vh3);
                    MMA16816(os[bg2 * 2 + 1], ah[0], ah[1], ah[2], ah[3], vl2, vl3);
                    MMA16816(os[bg2 * 2 + 1], al[0], al[1], al[2], al[3], vh2, vh3);
                }
            }
        }
        __syncthreads();    // all warps done with buf before it's overwritten
    }

    // ---- epilogue: context as hi/lo fp16 at [b, s, h*128 + d] ----
    const float inv0 = 1.0f / lrow[0];
    const float inv1 = 1.0f / lrow[1];
    const int row0 = q0 + wid * 16 + (lid >> 2);
    const int dbase = 2 * (lid & 3);
    #pragma unroll
    for (int nt = 0; nt < 16; nt++) {
        int d = nt * 8 + dbase;
        size_t i0 = ((size_t)(b * SEQ + row0))     * EMB + h * HDIM + d;
        size_t i1 = ((size_t)(b * SEQ + row0 + 8)) * EMB + h * HDIM + d;
        uint32_t hp, lp;
        split_hl(os[nt][0] * inv0, os[nt][1] * inv0, hp, lp);
        *(uint32_t*)(Ch + i0) = hp;
        *(uint32_t*)(Cl + i0) = lp;
        split_hl(os[nt][2] * inv1, os[nt][3] * inv1, hp, lp);
        *(uint32_t*)(Ch + i1) = hp;
        *(uint32_t*)(Cl + i1) = lp;
    }
}

// =================================================================================
extern "C" void kernel_launch(void* const* d_in, const int* in_sizes, int n_in,
                              void* d_out, int out_size)
{
    const float* x  = (const float*)d_in[0];
    const float* Wq = (const float*)d_in[1];
    const float* Wk = (const float*)d_in[2];
    const float* Wv = (const float*)d_in[3];
    const float* Wo = (const float*)d_in[4];
    float* out = (float*)d_out;

    __half *xh, *xl, *Wh, *Wl, *Qh, *Ql, *Kh, *Kl, *Vh, *Vl, *Ch, *Cl;
    cudaGetSymbolAddress((void**)&xh, g_xh);
    cudaGetSymbolAddress((void**)&xl, g_xl);
    cudaGetSymbolAddress((void**)&Wh, g_Wh);
    cudaGetSymbolAddress((void**)&Wl, g_Wl);
    cudaGetSymbolAddress((void**)&Qh, g_Qh);
    cudaGetSymbolAddress((void**)&Ql, g_Ql);
    cudaGetSymbolAddress((void**)&Kh, g_Kh);
    cudaGetSymbolAddress((void**)&Kl, g_Kl);
    cudaGetSymbolAddress((void**)&Vh, g_Vh);
    cudaGetSymbolAddress((void**)&Vl, g_Vl);
    cudaGetSymbolAddress((void**)&Ch, g_Ch);
    cudaGetSymbolAddress((void**)&Cl, g_Cl);

    cudaFuncSetAttribute(gemm_hl<1>, cudaFuncAttributeMaxDynamicSharedMemorySize, GSM);
    cudaFuncSetAttribute(gemm_hl<0>, cudaFuncAttributeMaxDynamicSharedMemorySize, GSM);
    cudaFuncSetAttribute(flash_mma, cudaFuncAttributeMaxDynamicSharedMemorySize, FH_BYTES);

    // 0) pre-convert inputs to fp16 hi/lo
    conv_hl<<<NELEM_X / 1024, 256>>>(x,  xh, xl);
    conv_hl<<<NELEM_W / 1024, 256>>>(Wq, Wh + 0 * NELEM_W, Wl + 0 * NELEM_W);
    conv_hl<<<NELEM_W / 1024, 256>>>(Wk, Wh + 1 * NELEM_W, Wl + 1 * NELEM_W);
    conv_hl<<<NELEM_W / 1024, 256>>>(Wv, Wh + 2 * NELEM_W, Wl + 2 * NELEM_W);
    conv_hl<<<NELEM_W / 1024, 256>>>(Wo, Wh + 3 * NELEM_W, Wl + 3 * NELEM_W);

    // 1) fused QKV projection + RoPE -> hi/lo [B,H,S,D]
    {
        dim3 grid(EMB / BN, MTOT / BM, 3);
        gemm_hl<1><<<grid, 256, GSM>>>(
            xh, xl,
            Wh + 0 * NELEM_W, Wl + 0 * NELEM_W,
            Wh + 1 * NELEM_W, Wl + 1 * NELEM_W,
            Wh + 2 * NELEM_W, Wl + 2 * NELEM_W,
            Qh, Ql, Kh, Kl, Vh, Vl, nullptr);
    }
    // 2) causal flash attention -> context hi/lo
    {
        dim3 grid(SEQ / 128, BATCH * NHEAD);
        flash_mma<<<grid, 256, FH_BYTES>>>(Qh, Ql, Kh, Kl, Vh, Vl, Ch, Cl);
    }
    // 3) output projection -> fp32 out
    {
        dim3 grid(EMB / BN, MTOT / BM, 1);
        gemm_hl<0><<<grid, 256, GSM>>>(
            Ch, Cl,
            Wh + 3 * NELEM_W, Wl + 3 * NELEM_W,
            nullptr, nullptr, nullptr, nullptr,
            nullptr, nullptr, nullptr, nullptr, nullptr, nullptr, out);
    }
}